// round 17
// baseline (speedup 1.0000x reference)
#include <cuda_runtime.h>
#include <cstdint>
#include <float.h>

#define BB 4
#define NN 40960
#define KK 16
#define DD 64
#define HH 32
#define NPTS (BB * NN)
#define EPSV 1e-5f
#define PPW 16   // points per warp

typedef unsigned long long ull;
typedef unsigned int u32;

// ---------- helpers ----------
__device__ __forceinline__ u32 cvt_tf32(float f) {
    u32 r;
    asm("cvt.rna.tf32.f32 %0, %1;" : "=r"(r) : "f"(f));
    return r;
}
__device__ __forceinline__ void mma_tf32(float& c0, float& c1, float& c2, float& c3,
                                         u32 a0, u32 a1, u32 a2, u32 a3, u32 b0, u32 b1) {
    asm("mma.sync.aligned.m16n8k8.row.col.f32.tf32.tf32.f32 "
        "{%0,%1,%2,%3}, {%4,%5,%6,%7}, {%8,%9}, {%0,%1,%2,%3};"
        : "+f"(c0), "+f"(c1), "+f"(c2), "+f"(c3)
        : "r"(a0), "r"(a1), "r"(a2), "r"(a3), "r"(b0), "r"(b1));
}
__device__ __forceinline__ u32 smem_u32(const void* p) {
    return (u32)__cvta_generic_to_shared(p);
}
__device__ __forceinline__ void split_tf32(float v, u32& hi, u32& lo) {
    hi = cvt_tf32(v);
    lo = cvt_tf32(v - __uint_as_float(hi));
}

// ---------- folded weights ----------
__device__ u32 dW2tfH[HH * DD], dW2tfL[HH * DD];    // [h][c] h<32, c<64 (pass1, 3xtf32)
__device__ u32 dW3AtfH[HH * HH], dW3AtfL[HH * HH];  // [h][c] (pass1)
__device__ u32 dW4BtfH[DD * HH], dW4BtfL[DD * HH];  // [d][c] = s4*W4[d][32+c] (pass1)
__device__ u32 dW3Btf[HH * HH];                     // [h][c] tf32 (pass2)
__device__ u32 dW4Atf[DD * HH];                     // [d][c] tf32 (pass2 epilogue)
__device__ float4 dCoefA[HH];                       // (m1x, m1y, m1z, w1d)
__device__ float4 dCoefB[HH];                       // (m0x, m0y, m0z, b1)
__device__ float dB2[HH], dB3[HH], dB4[DD];
__device__ int dIdx64;

// ---------- scratch ----------
__device__ float dE[NPTS * DD];      // E = W4b@f + b4
__device__ float dG[NPTS * HH];      // G = s3*(W3a@f)+b3, C-frag layout
__device__ float dFC[NPTS * HH];     // fc scratch (pass2 warp-private)
__device__ float4 dXYZ4[NPTS];
__device__ int dIdx32buf[NPTS * KK];

// ================== prep ==================
__global__ void prep_kernel(const float* __restrict__ W1, const float* __restrict__ W2,
                            const float* __restrict__ W3, const float* __restrict__ W4,
                            const float* __restrict__ g1, const float* __restrict__ b1,
                            const float* __restrict__ g2, const float* __restrict__ b2,
                            const float* __restrict__ g3, const float* __restrict__ b3,
                            const float* __restrict__ g4, const float* __restrict__ b4) {
    int t = threadIdx.x;
    float inv = rsqrtf(1.0f + EPSV);
    for (int i = t; i < HH * DD; i += blockDim.x) {
        int h = i >> 6, c = i & 63;
        float v = g2[h] * inv * W2[h * DD + c];
        split_tf32(v, dW2tfH[i], dW2tfL[i]);
    }
    for (int i = t; i < HH * HH; i += blockDim.x) {
        int h = i >> 5, c = i & 31;
        float v = g3[h] * inv * W3[h * (2 * HH) + c];
        split_tf32(v, dW3AtfH[i], dW3AtfL[i]);
        dW3Btf[i] = cvt_tf32(g3[h] * inv * W3[h * (2 * HH) + HH + c]);
    }
    for (int i = t; i < DD * HH; i += blockDim.x) {
        int d = i >> 5, c = i & 31;
        float v = g4[d] * inv * W4[d * (2 * HH) + HH + c];
        split_tf32(v, dW4BtfH[i], dW4BtfL[i]);
        dW4Atf[i] = cvt_tf32(g4[d] * inv * W4[d * (2 * HH) + c]);
    }
    for (int c = t; c < HH; c += blockDim.x) {
        float s = g1[c] * inv;
        dCoefA[c] = make_float4(s * (W1[c * 10 + 7] - W1[c * 10 + 1]),
                                s * (W1[c * 10 + 8] - W1[c * 10 + 2]),
                                s * (W1[c * 10 + 9] - W1[c * 10 + 3]),
                                s * W1[c * 10 + 0]);
        dCoefB[c] = make_float4(s * (W1[c * 10 + 1] + W1[c * 10 + 4]),
                                s * (W1[c * 10 + 2] + W1[c * 10 + 5]),
                                s * (W1[c * 10 + 3] + W1[c * 10 + 6]),
                                b1[c]);
        dB2[c] = b2[c];
        dB3[c] = b3[c];
    }
    for (int d = t; d < DD; d += blockDim.x) dB4[d] = b4[d];
}

// ================== detect int64 vs int32 neigh_idx ==================
__global__ void detect_kernel(const unsigned int* __restrict__ w) {
    __shared__ int sBad;
    if (threadIdx.x == 0) sBad = 0;
    __syncthreads();
    unsigned int acc = 0;
    for (int i = threadIdx.x; i < 2048; i += blockDim.x) acc |= w[2 * i + 1];
    if (acc) atomicOr(&sBad, 1);
    __syncthreads();
    if (threadIdx.x == 0) dIdx64 = (sBad == 0) ? 1 : 0;
}

// ================== narrow neigh_idx to int32 ==================
__global__ void convert_kernel(const unsigned int* __restrict__ idxw) {
    int i = blockIdx.x * 256 + threadIdx.x;
    dIdx32buf[i] = (int)idxw[(size_t)i << dIdx64];
}

// ================== pass 1 (tensor-core): f, G, E, xyz4 ==================
// warp-per-16-points; 3xtf32 split precision; weights as B-fragments from L1.
__global__ void __launch_bounds__(256, 2) pass1_kernel(const float* __restrict__ feat,
                                                       const float* __restrict__ xyz) {
    __shared__ float sF[8][16 * 34];  // per-warp f tile, 8B-aligned rows (pad 34)
    int tid = threadIdx.x, lane = tid & 31, warp = tid >> 5;
    int gid = lane >> 2, tig = lane & 3;
    int p0 = blockIdx.x * 128 + warp * PPW;
    int b = p0 / NN, n0 = p0 - b * NN;
    const float* fb = feat + (size_t)b * DD * NN + n0;

    // xyz4 for this block's 128 points
    if (tid < 128) {
        int pp = blockIdx.x * 128 + tid;
        const float* xp = xyz + (size_t)pp * 3;
        dXYZ4[pp] = make_float4(xp[0], xp[1], xp[2], 0.0f);
    }

    // ---- load feat A-fragments (fully-used 32B sectors), split hi/lo ----
    u32 AH[8][4], AL[8][4];
#pragma unroll
    for (int s = 0; s < 8; s++) {
        int c = 8 * s + tig;
        float a0 = fb[(size_t)c * NN + gid];
        float a1 = fb[(size_t)c * NN + gid + 8];
        float a2 = fb[(size_t)(c + 4) * NN + gid];
        float a3 = fb[(size_t)(c + 4) * NN + gid + 8];
        split_tf32(a0, AH[s][0], AL[s][0]);
        split_tf32(a1, AH[s][1], AL[s][1]);
        split_tf32(a2, AH[s][2], AL[s][2]);
        split_tf32(a3, AH[s][3], AL[s][3]);
    }

    // ---- f = relu(W2 @ feat + b2)  [16 pts x 32 out] ----
    float C2[4][4];
#pragma unroll
    for (int nt = 0; nt < 4; nt++) {
        float b20 = dB2[nt * 8 + 2 * tig], b21 = dB2[nt * 8 + 2 * tig + 1];
        C2[nt][0] = b20; C2[nt][1] = b21; C2[nt][2] = b20; C2[nt][3] = b21;
    }
#pragma unroll
    for (int s = 0; s < 8; s++)
#pragma unroll
        for (int nt = 0; nt < 4; nt++) {
            const u32* WH = dW2tfH + (nt * 8 + gid) * DD + 8 * s + tig;
            const u32* WL = dW2tfL + (nt * 8 + gid) * DD + 8 * s + tig;
            u32 bh0 = WH[0], bh1 = WH[4], bl0 = WL[0], bl1 = WL[4];
            mma_tf32(C2[nt][0], C2[nt][1], C2[nt][2], C2[nt][3],
                     AH[s][0], AH[s][1], AH[s][2], AH[s][3], bh0, bh1);
            mma_tf32(C2[nt][0], C2[nt][1], C2[nt][2], C2[nt][3],
                     AH[s][0], AH[s][1], AH[s][2], AH[s][3], bl0, bl1);
            mma_tf32(C2[nt][0], C2[nt][1], C2[nt][2], C2[nt][3],
                     AL[s][0], AL[s][1], AL[s][2], AL[s][3], bh0, bh1);
        }

    // relu, round-trip through per-warp smem to reshape C-frag -> A-frag
    float* fw = sF[warp];
#pragma unroll
    for (int nt = 0; nt < 4; nt++) {
        *(float2*)&fw[gid * 34 + nt * 8 + 2 * tig] =
            make_float2(fmaxf(C2[nt][0], 0.0f), fmaxf(C2[nt][1], 0.0f));
        *(float2*)&fw[(gid + 8) * 34 + nt * 8 + 2 * tig] =
            make_float2(fmaxf(C2[nt][2], 0.0f), fmaxf(C2[nt][3], 0.0f));
    }
    __syncwarp();

    u32 FH[4][4], FL[4][4];
#pragma unroll
    for (int s = 0; s < 4; s++) {
        int c = 8 * s + tig;
        split_tf32(fw[gid * 34 + c], FH[s][0], FL[s][0]);
        split_tf32(fw[(gid + 8) * 34 + c], FH[s][1], FL[s][1]);
        split_tf32(fw[gid * 34 + c + 4], FH[s][2], FL[s][2]);
        split_tf32(fw[(gid + 8) * 34 + c + 4], FH[s][3], FL[s][3]);
    }

    // ---- G = W3a @ f + b3  [16 x 32] ----
    float C3[4][4];
#pragma unroll
    for (int nt = 0; nt < 4; nt++) {
        float b30 = dB3[nt * 8 + 2 * tig], b31 = dB3[nt * 8 + 2 * tig + 1];
        C3[nt][0] = b30; C3[nt][1] = b31; C3[nt][2] = b30; C3[nt][3] = b31;
    }
#pragma unroll
    for (int s = 0; s < 4; s++)
#pragma unroll
        for (int nt = 0; nt < 4; nt++) {
            const u32* WH = dW3AtfH + (nt * 8 + gid) * HH + 8 * s + tig;
            const u32* WL = dW3AtfL + (nt * 8 + gid) * HH + 8 * s + tig;
            u32 bh0 = WH[0], bh1 = WH[4], bl0 = WL[0], bl1 = WL[4];
            mma_tf32(C3[nt][0], C3[nt][1], C3[nt][2], C3[nt][3],
                     FH[s][0], FH[s][1], FH[s][2], FH[s][3], bh0, bh1);
            mma_tf32(C3[nt][0], C3[nt][1], C3[nt][2], C3[nt][3],
                     FH[s][0], FH[s][1], FH[s][2], FH[s][3], bl0, bl1);
            mma_tf32(C3[nt][0], C3[nt][1], C3[nt][2], C3[nt][3],
                     FL[s][0], FL[s][1], FL[s][2], FL[s][3], bh0, bh1);
        }
#pragma unroll
    for (int nt = 0; nt < 4; nt++) {
        *(float2*)(dG + (size_t)(p0 + gid) * HH + tig * 8 + nt * 2) =
            make_float2(C3[nt][0], C3[nt][1]);
        *(float2*)(dG + (size_t)(p0 + gid + 8) * HH + tig * 8 + nt * 2) =
            make_float2(C3[nt][2], C3[nt][3]);
    }

    // ---- E = W4b @ f + b4  [16 x 64] ----
    float C4[8][4];
#pragma unroll
    for (int nt = 0; nt < 8; nt++) {
        float b40 = dB4[nt * 8 + 2 * tig], b41 = dB4[nt * 8 + 2 * tig + 1];
        C4[nt][0] = b40; C4[nt][1] = b41; C4[nt][2] = b40; C4[nt][3] = b41;
    }
#pragma unroll
    for (int s = 0; s < 4; s++)
#pragma unroll
        for (int nt = 0; nt < 8; nt++) {
            const u32* WH = dW4BtfH + (nt * 8 + gid) * HH + 8 * s + tig;
            const u32* WL = dW4BtfL + (nt * 8 + gid) * HH + 8 * s + tig;
            u32 bh0 = WH[0], bh1 = WH[4], bl0 = WL[0], bl1 = WL[4];
            mma_tf32(C4[nt][0], C4[nt][1], C4[nt][2], C4[nt][3],
                     FH[s][0], FH[s][1], FH[s][2], FH[s][3], bh0, bh1);
            mma_tf32(C4[nt][0], C4[nt][1], C4[nt][2], C4[nt][3],
                     FH[s][0], FH[s][1], FH[s][2], FH[s][3], bl0, bl1);
            mma_tf32(C4[nt][0], C4[nt][1], C4[nt][2], C4[nt][3],
                     FL[s][0], FL[s][1], FL[s][2], FL[s][3], bh0, bh1);
        }
#pragma unroll
    for (int nt = 0; nt < 8; nt++) {
        *(float2*)(dE + (size_t)(p0 + gid) * DD + nt * 8 + 2 * tig) =
            make_float2(C4[nt][0], C4[nt][1]);
        *(float2*)(dE + (size_t)(p0 + gid + 8) * DD + nt * 8 + 2 * tig) =
            make_float2(C4[nt][2], C4[nt][3]);
    }
}

// ================== pass 2: gather + tf32 MMA + max-pool + fused W4a epilogue ==================
#define RS 36

__global__ void __launch_bounds__(256, 2) pass2_kernel(float* __restrict__ out) {
    __shared__ float sG[2][8][16 * RS];
    __shared__ int sIdx[8][256];
    __shared__ float4 sCA[HH], sCB[HH];
    int tid = threadIdx.x;
    if (tid < HH) { sCA[tid] = dCoefA[tid]; sCB[tid] = dCoefB[tid]; }
    {
        const int4* src = (const int4*)dIdx32buf + (size_t)blockIdx.x * 512;
        int4* dst = (int4*)sIdx;
        for (int t = tid; t < 512; t += 256) dst[t] = src[t];
    }
    __syncthreads();

    int lane = tid & 31, warp = tid >> 5;
    int gid = lane >> 2, tig = lane & 3;

    u32 B[4][4][2];
#pragma unroll
    for (int s = 0; s < 4; s++)
#pragma unroll
        for (int nt = 0; nt < 4; nt++) {
            B[s][nt][0] = dW3Btf[(nt * 8 + gid) * HH + 8 * s + tig];
            B[s][nt][1] = dW3Btf[(nt * 8 + gid) * HH + 8 * s + tig + 4];
        }

    int pbase = (blockIdx.x * 8 + warp) * PPW;
    int bBase = (pbase / NN) * NN;
    const int* iw = sIdx[warp];
    float* buf0 = sG[0][warp];
    float* buf1 = sG[1][warp];

#define STAGE(I, BUF)                                                                  \
    {                                                                                  \
        _Pragma("unroll")                                                              \
        for (int u = 0; u < 5; u++) {                                                  \
            int c = u * 32 + lane;                                                     \
            if (c < 144) {                                                             \
                int row = c / 9;                                                       \
                int ch = c - row * 9;                                                  \
                int j = bBase + iw[(I) * 16 + row];                                    \
                const float* src = (ch < 8) ? (dG + (size_t)j * HH + ch * 4)           \
                                            : (const float*)(dXYZ4 + j);               \
                u32 dst = smem_u32((BUF) + row * RS + ch * 4);                         \
                asm volatile("cp.async.cg.shared.global [%0], [%1], 16;"               \
                             :: "r"(dst), "l"(src));                                   \
            }                                                                          \
        }                                                                              \
        asm volatile("cp.async.commit_group;");                                        \
    }

    STAGE(0, buf0);

#pragma unroll 1
    for (int i = 0; i < PPW; i++) {
        float* cbuf = (i & 1) ? buf1 : buf0;
        float* nbuf = (i & 1) ? buf0 : buf1;
        if (i < PPW - 1) {
            STAGE(i + 1, nbuf);
            asm volatile("cp.async.wait_group 1;");
        } else {
            asm volatile("cp.async.wait_group 0;");
        }
        __syncwarp();

        int p = pbase + i;
        float4 xc = dXYZ4[p];
        float4 xa = *(const float4*)(cbuf + gid * RS + 32);
        float4 xb = *(const float4*)(cbuf + (gid + 8) * RS + 32);

        const float4* g0p = (const float4*)(cbuf + gid * RS + tig * 8);
        const float4* g1p = (const float4*)(cbuf + (gid + 8) * RS + tig * 8);
        float4 qa0 = g0p[0], qa1 = g0p[1];
        float4 qb0 = g1p[0], qb1 = g1p[1];
        float C[4][4];
        C[0][0] = qa0.x; C[0][1] = qa0.y; C[1][0] = qa0.z; C[1][1] = qa0.w;
        C[2][0] = qa1.x; C[2][1] = qa1.y; C[3][0] = qa1.z; C[3][1] = qa1.w;
        C[0][2] = qb0.x; C[0][3] = qb0.y; C[1][2] = qb0.z; C[1][3] = qb0.w;
        C[2][2] = qb1.x; C[2][3] = qb1.y; C[3][2] = qb1.z; C[3][3] = qb1.w;

        float dxa = xc.x - xa.x, dya = xc.y - xa.y, dza = xc.z - xa.z;
        float dis0 = sqrtf(dxa * dxa + dya * dya + dza * dza);
        float dxb = xc.x - xb.x, dyb = xc.y - xb.y, dzb = xc.z - xb.z;
        float dis1 = sqrtf(dxb * dxb + dyb * dyb + dzb * dzb);

        u32 A[4][4];
#pragma unroll
        for (int t = 0; t < 8; t++) {
            float4 ca = sCA[tig + 4 * t];
            float4 cb = sCB[tig + 4 * t];
            float bb = fmaf(cb.x, xc.x, fmaf(cb.y, xc.y, fmaf(cb.z, xc.z, cb.w)));
            float v0 = fmaxf(fmaf(ca.x, xa.x, fmaf(ca.y, xa.y, fmaf(ca.z, xa.z, fmaf(ca.w, dis0, bb)))), 0.0f);
            float v1 = fmaxf(fmaf(ca.x, xb.x, fmaf(ca.y, xb.y, fmaf(ca.z, xb.z, fmaf(ca.w, dis1, bb)))), 0.0f);
            int s = t >> 1;
            if ((t & 1) == 0) { A[s][0] = cvt_tf32(v0); A[s][1] = cvt_tf32(v1); }
            else              { A[s][2] = cvt_tf32(v0); A[s][3] = cvt_tf32(v1); }
        }

#pragma unroll
        for (int s = 0; s < 4; s++)
#pragma unroll
            for (int nt = 0; nt < 4; nt++)
                mma_tf32(C[nt][0], C[nt][1], C[nt][2], C[nt][3],
                         A[s][0], A[s][1], A[s][2], A[s][3], B[s][nt][0], B[s][nt][1]);

        float r0[4], r1[4];
#pragma unroll
        for (int nt = 0; nt < 4; nt++) {
            r0[nt] = fmaxf(C[nt][0], C[nt][2]);
            r1[nt] = fmaxf(C[nt][1], C[nt][3]);
        }
#pragma unroll
        for (int off = 4; off <= 16; off <<= 1)
#pragma unroll
            for (int nt = 0; nt < 4; nt++) {
                r0[nt] = fmaxf(r0[nt], __shfl_xor_sync(0xffffffffu, r0[nt], off));
                r1[nt] = fmaxf(r1[nt], __shfl_xor_sync(0xffffffffu, r1[nt], off));
            }
        if (gid == 0) {
#pragma unroll
            for (int nt = 0; nt < 4; nt++) {
                float2 v = make_float2(fmaxf(r0[nt], 0.0f), fmaxf(r1[nt], 0.0f));
                *(float2*)(dFC + (size_t)p * HH + nt * 8 + 2 * tig) = v;
            }
        }
    }
#undef STAGE

    // ---- fused epilogue: out = relu(W4a @ fc + E) ----
    __syncwarp();
    u32 Af[4][4];
    const float* fcb = dFC + (size_t)pbase * HH;
#pragma unroll
    for (int s = 0; s < 4; s++) {
        Af[s][0] = cvt_tf32(fcb[gid * HH + 8 * s + tig]);
        Af[s][1] = cvt_tf32(fcb[(gid + 8) * HH + 8 * s + tig]);
        Af[s][2] = cvt_tf32(fcb[gid * HH + 8 * s + tig + 4]);
        Af[s][3] = cvt_tf32(fcb[(gid + 8) * HH + 8 * s + tig + 4]);
    }
    int bOut = pbase / NN;
    float* outB = out + (size_t)bOut * DD * NN;
    int n0 = pbase - bOut * NN;
#pragma unroll
    for (int nt = 0; nt < 8; nt++) {
        float2 e0 = *(const float2*)(dE + (size_t)(pbase + gid) * DD + nt * 8 + 2 * tig);
        float2 e1 = *(const float2*)(dE + (size_t)(pbase + gid + 8) * DD + nt * 8 + 2 * tig);
        float c0 = e0.x, c1 = e0.y, c2 = e1.x, c3 = e1.y;
#pragma unroll
        for (int s = 0; s < 4; s++) {
            u32 b0 = dW4Atf[(nt * 8 + gid) * HH + 8 * s + tig];
            u32 b1 = dW4Atf[(nt * 8 + gid) * HH + 8 * s + tig + 4];
            mma_tf32(c0, c1, c2, c3, Af[s][0], Af[s][1], Af[s][2], Af[s][3], b0, b1);
        }
        int d0 = nt * 8 + 2 * tig;
        outB[(size_t)d0 * NN + n0 + gid] = fmaxf(c0, 0.0f);
        outB[(size_t)(d0 + 1) * NN + n0 + gid] = fmaxf(c1, 0.0f);
        outB[(size_t)d0 * NN + n0 + gid + 8] = fmaxf(c2, 0.0f);
        outB[(size_t)(d0 + 1) * NN + n0 + gid + 8] = fmaxf(c3, 0.0f);
    }
}

// ================== launch ==================
extern "C" void kernel_launch(void* const* d_in, const int* in_sizes, int n_in,
                              void* d_out, int out_size) {
    const float *feat, *xyz, *W1, *W2, *W3, *W4;
    const float *g1, *b1, *g2, *b2, *g3, *b3, *g4, *b4;
    const void* idx;
    if (n_in >= 3 && in_sizes[2] == 320) {
        feat = (const float*)d_in[0];  xyz = (const float*)d_in[1];
        W1 = (const float*)d_in[2];    g1 = (const float*)d_in[3];  b1 = (const float*)d_in[4];
        W2 = (const float*)d_in[5];    g2 = (const float*)d_in[6];  b2 = (const float*)d_in[7];
        W3 = (const float*)d_in[8];    g3 = (const float*)d_in[9];  b3 = (const float*)d_in[10];
        W4 = (const float*)d_in[11];   g4 = (const float*)d_in[12]; b4 = (const float*)d_in[13];
        idx = d_in[14];
    } else {
        feat = (const float*)d_in[0];  xyz = (const float*)d_in[1];  idx = d_in[2];
        W1 = (const float*)d_in[3];    W2 = (const float*)d_in[4];
        W3 = (const float*)d_in[5];    W4 = (const float*)d_in[6];
        g1 = (const float*)d_in[7];    b1 = (const float*)d_in[8];
        g2 = (const float*)d_in[9];    b2 = (const float*)d_in[10];
        g3 = (const float*)d_in[11];   b3 = (const float*)d_in[12];
        g4 = (const float*)d_in[13];   b4 = (const float*)d_in[14];
    }
    prep_kernel<<<1, 256>>>(W1, W2, W3, W4, g1, b1, g2, b2, g3, b3, g4, b4);
    detect_kernel<<<1, 256>>>((const unsigned int*)idx);
    convert_kernel<<<NPTS * KK / 256, 256>>>((const unsigned int*)idx);
    pass1_kernel<<<NPTS / 128, 256>>>(feat, xyz);
    pass2_kernel<<<NPTS / (8 * PPW), 256>>>((float*)d_out);
}